// round 10
// baseline (speedup 1.0000x reference)
#include <cuda_runtime.h>
#include <cuda_bf16.h>
#include <math.h>
#include <cstdint>

#define BATCH 131072
#define SD 64
#define CD 16
#define HID 256

// ---------------- smem layout (bytes) ----------------
#define SM_A2H   0         // 128 rows x 264 halves (528B stride) = 67584
#define SM_A2L   67584
#define SM_WH    135168    // 256 n-rows x 72 halves (144B stride) = 36864
#define SM_WL    172032
#define SM_W3H   135168    // reuse W buffer: 16 x 264 halves (528B) = 8448
#define SM_W3L   143616
#define SM_B1    208896    // 256 f32
#define SM_B2    209920    // 256 f32
#define SM_B3B   210944    // 16 f32
#define SM_TOTAL 211008

// ---------------- scratch globals ----------------
__device__ float g_W3B[HID * CD];
__device__ float g_b3B[CD];
__device__ float g_pB[BATCH * CD];
__device__ int   g_K;

// ---------------- helpers ----------------
__device__ __forceinline__ uint32_t smem_u32(const void* p) {
    uint32_t a;
    asm("{ .reg .u64 t; cvta.to.shared.u64 t, %1; cvt.u32.u64 %0, t; }" : "=r"(a) : "l"(p));
    return a;
}

// split (a,b) f32 pair into packed bf16x2 hi + lo (residual)
__device__ __forceinline__ void split2(float a, float b, uint32_t& hi, uint32_t& lo) {
    __nv_bfloat16 ha = __float2bfloat16(a), hb = __float2bfloat16(b);
    float ra = a - __bfloat162float(ha);
    float rb = b - __bfloat162float(hb);
    __nv_bfloat16 la = __float2bfloat16(ra), lb = __float2bfloat16(rb);
    hi = ((uint32_t)__bfloat16_as_ushort(hb) << 16) | (uint32_t)__bfloat16_as_ushort(ha);
    lo = ((uint32_t)__bfloat16_as_ushort(lb) << 16) | (uint32_t)__bfloat16_as_ushort(la);
}

#define LDSM4(v, addr) \
    asm volatile("ldmatrix.sync.aligned.m8n8.x4.shared.b16 {%0,%1,%2,%3}, [%4];" \
        : "=r"((v)[0]), "=r"((v)[1]), "=r"((v)[2]), "=r"((v)[3]) : "r"(addr))

#define MMA(d, a, b0, b1) \
    asm volatile("mma.sync.aligned.m16n8k16.row.col.f32.bf16.bf16.f32 " \
        "{%0,%1,%2,%3}, {%4,%5,%6,%7}, {%8,%9}, {%0,%1,%2,%3};" \
        : "+f"((d)[0]), "+f"((d)[1]), "+f"((d)[2]), "+f"((d)[3]) \
        : "r"((a)[0]), "r"((a)[1]), "r"((a)[2]), "r"((a)[3]), "r"(b0), "r"(b1))

// ---------------- k_prep: parallel W3B = W3 @ Bmat ----------------
// grid 17: blocks 0..15 each compute one output column j of W3B (256 rows);
// block 16 computes b3B and resets g_K.
__global__ void k_prep(const float* __restrict__ W3, const float* __restrict__ b3,
                       const float* __restrict__ Bm) {
    int blk = blockIdx.x;
    int h = threadIdx.x;
    if (blk < CD) {
        int j = blk;
        float a = 0.0f;
        for (int d = 0; d < SD; d++) a = fmaf(W3[h * SD + d], Bm[d * CD + j], a);
        g_W3B[h * CD + j] = a;
    } else {
        if (h < CD) {
            float a = 0.0f;
            for (int d = 0; d < SD; d++) a = fmaf(b3[d], Bm[d * CD + h], a);
            g_b3B[h] = a;
        }
        if (h == 0) g_K = 0;
    }
}

// stage W chunk [64 k x 256 n] f32 -> Wt[n][k] bf16 hi/lo
__device__ __forceinline__ void load_wchunk(char* sm, const float* __restrict__ W,
                                            int krow0, int tid) {
    int n = tid;
#pragma unroll
    for (int it = 0; it < 8; it++) {
        int kb = krow0 + it * 8;
        uint32_t h[4], l[4];
#pragma unroll
        for (int q = 0; q < 4; q++) {
            float w0 = W[(kb + 2 * q) * HID + n];
            float w1 = W[(kb + 2 * q + 1) * HID + n];
            split2(w0, w1, h[q], l[q]);
        }
        *(uint4*)(sm + SM_WH + n * 144 + it * 16) = make_uint4(h[0], h[1], h[2], h[3]);
        *(uint4*)(sm + SM_WL + n * 144 + it * 16) = make_uint4(l[0], l[1], l[2], l[3]);
    }
}

// ---------------- fused MLP via mma.sync (bf16 3-product everywhere) ----------------
__global__ void __launch_bounds__(256, 1) k_mlp(
    const float* __restrict__ x, const float* __restrict__ t,
    const float* __restrict__ W1, const float* __restrict__ b1,
    const float* __restrict__ W2, const float* __restrict__ b2)
{
    extern __shared__ char sm[];
    uint32_t smb = smem_u32(sm);
    int tid = threadIdx.x, wid = tid >> 5, lid = tid & 31;
    int slab = wid * 16;
    int row0 = blockIdx.x * 128;
    int r0 = lid >> 2, cq = 2 * (lid & 3);

    // coop: biases + W1 chunk
    float t0 = t[0];
    ((float*)(sm + SM_B1))[tid] = fmaf(t0, W1[64 * HID + tid], b1[tid]);
    ((float*)(sm + SM_B2))[tid] = b2[tid];
    if (tid < CD) ((float*)(sm + SM_B3B))[tid] = g_b3B[tid];
    load_wchunk(sm, W1, 0, tid);

    // per-warp: stage own 16 rows of X into own region of A2H, stride 68 f32
    float* Xs = (float*)(sm + SM_A2H + wid * 8448);
#pragma unroll
    for (int i = 0; i < 8; i++) {
        int fid = i * 32 + lid;
        int r = fid >> 4, c4 = fid & 15;
        float4 v = *(const float4*)&x[(row0 + slab + r) * SD + c4 * 4];
        *(float4*)&Xs[r * 68 + c4 * 4] = v;
    }
    __syncwarp();

    // X fragments (bf16 hi/lo) in regs: 4 k-tiles
    uint32_t xh[4][4], xl[4][4];
#pragma unroll
    for (int kt = 0; kt < 4; kt++) {
        int cb = kt * 16 + cq;
        float2 v00 = *(float2*)&Xs[r0 * 68 + cb];
        float2 v10 = *(float2*)&Xs[(r0 + 8) * 68 + cb];
        float2 v01 = *(float2*)&Xs[r0 * 68 + cb + 8];
        float2 v11 = *(float2*)&Xs[(r0 + 8) * 68 + cb + 8];
        split2(v00.x, v00.y, xh[kt][0], xl[kt][0]);
        split2(v10.x, v10.y, xh[kt][1], xl[kt][1]);
        split2(v01.x, v01.y, xh[kt][2], xl[kt][2]);
        split2(v11.x, v11.y, xh[kt][3], xl[kt][3]);
    }
    __syncwarp();
    __syncthreads();

    // ---- Layer 1: D[16x256] = X @ W1 (bf16 3-product) ----
    float d[32][4];
#pragma unroll
    for (int m = 0; m < 32; m++)
#pragma unroll
        for (int q = 0; q < 4; q++) d[m][q] = 0.0f;

#pragma unroll
    for (int kt = 0; kt < 4; kt++) {
#pragma unroll
        for (int n2 = 0; n2 < 16; n2++) {
            uint32_t bh[4], bl[4];
            uint32_t brow = n2 * 16 + ((lid >> 4) << 3) + (lid & 7);
            uint32_t baddr = smb + SM_WH + brow * 144 + (kt * 16 + (lid & 8)) * 2;
            LDSM4(bh, baddr);
            LDSM4(bl, baddr + (SM_WL - SM_WH));
            MMA(d[2 * n2],     xh[kt], bh[0], bh[1]);
            MMA(d[2 * n2],     xh[kt], bl[0], bl[1]);
            MMA(d[2 * n2],     xl[kt], bh[0], bh[1]);
            MMA(d[2 * n2 + 1], xh[kt], bh[2], bh[3]);
            MMA(d[2 * n2 + 1], xh[kt], bl[2], bl[3]);
            MMA(d[2 * n2 + 1], xl[kt], bh[2], bh[3]);
        }
    }

    // ---- relu + bias1 -> A2 (warp-private smem, bf16 hi/lo) ----
    {
        const float* bs1 = (const float*)(sm + SM_B1);
#pragma unroll
        for (int m = 0; m < 32; m++) {
            int c = m * 8 + cq;
            float2 bv = *(const float2*)&bs1[c];
            float h0 = fmaxf(d[m][0] + bv.x, 0.0f);
            float h1 = fmaxf(d[m][1] + bv.y, 0.0f);
            float h2 = fmaxf(d[m][2] + bv.x, 0.0f);
            float h3 = fmaxf(d[m][3] + bv.y, 0.0f);
            uint32_t hi01, lo01, hi23, lo23;
            split2(h0, h1, hi01, lo01);
            split2(h2, h3, hi23, lo23);
            int ra = slab + r0;
            *(uint32_t*)(sm + SM_A2H + ra * 528 + c * 2) = hi01;
            *(uint32_t*)(sm + SM_A2L + ra * 528 + c * 2) = lo01;
            *(uint32_t*)(sm + SM_A2H + (ra + 8) * 528 + c * 2) = hi23;
            *(uint32_t*)(sm + SM_A2L + (ra + 8) * 528 + c * 2) = lo23;
        }
    }
    __syncthreads();

    // zero accum for layer 2
#pragma unroll
    for (int m = 0; m < 32; m++)
#pragma unroll
        for (int q = 0; q < 4; q++) d[m][q] = 0.0f;

    // ---- Layer 2: 4 K-chunks of 64 (bf16 3-product) ----
#pragma unroll 1
    for (int kc = 0; kc < 4; kc++) {
        load_wchunk(sm, W2, kc * 64, tid);
        __syncthreads();
#pragma unroll
        for (int kt = 0; kt < 4; kt++) {
            uint32_t ah[4], al[4];
            uint32_t arow = slab + (lid & 15);
            uint32_t acol = kc * 64 + kt * 16 + ((lid >> 4) << 3);
            uint32_t aaddr = smb + SM_A2H + arow * 528 + acol * 2;
            LDSM4(ah, aaddr);
            LDSM4(al, aaddr + (SM_A2L - SM_A2H));
#pragma unroll
            for (int n2 = 0; n2 < 16; n2++) {
                uint32_t bh[4], bl[4];
                uint32_t brow = n2 * 16 + ((lid >> 4) << 3) + (lid & 7);
                uint32_t baddr = smb + SM_WH + brow * 144 + (kt * 16 + (lid & 8)) * 2;
                LDSM4(bh, baddr);
                LDSM4(bl, baddr + (SM_WL - SM_WH));
                MMA(d[2 * n2],     ah, bh[0], bh[1]);
                MMA(d[2 * n2],     ah, bl[0], bl[1]);
                MMA(d[2 * n2],     al, bh[0], bh[1]);
                MMA(d[2 * n2 + 1], ah, bh[2], bh[3]);
                MMA(d[2 * n2 + 1], ah, bl[2], bl[3]);
                MMA(d[2 * n2 + 1], al, bh[2], bh[3]);
            }
        }
        __syncthreads();
    }

    // ---- stage W3B^T [16n x 256k] bf16 hi/lo into W buffer ----
#pragma unroll
    for (int it = 0; it < 8; it++) {
        int pid = tid + it * 256;
        int n = pid & 15, k2 = pid >> 4;
        float v0 = g_W3B[(2 * k2) * CD + n];
        float v1 = g_W3B[(2 * k2 + 1) * CD + n];
        uint32_t hi, lo;
        split2(v0, v1, hi, lo);
        *(uint32_t*)(sm + SM_W3H + n * 528 + k2 * 4) = hi;
        *(uint32_t*)(sm + SM_W3L + n * 528 + k2 * 4) = lo;
    }
    __syncthreads();

    // ---- relu + bias2 -> A3 fragments (bf16 hi/lo) ----
    uint32_t a3h[16][4], a3l[16][4];
    {
        const float* bs2 = (const float*)(sm + SM_B2);
#pragma unroll
        for (int g = 0; g < 16; g++) {
#pragma unroll
            for (int hh = 0; hh < 2; hh++) {
                int m = 2 * g + hh;
                int c = m * 8 + cq;
                float2 bv = *(const float2*)&bs2[c];
                float h0 = fmaxf(d[m][0] + bv.x, 0.0f);
                float h1 = fmaxf(d[m][1] + bv.y, 0.0f);
                float h2 = fmaxf(d[m][2] + bv.x, 0.0f);
                float h3 = fmaxf(d[m][3] + bv.y, 0.0f);
                split2(h0, h1, a3h[g][2 * hh],     a3l[g][2 * hh]);
                split2(h2, h3, a3h[g][2 * hh + 1], a3l[g][2 * hh + 1]);
            }
        }
    }

    // ---- Layer 3: pB[16x16] = H2 @ W3B (bf16 3-product) ----
    float d3a[4] = {0.f, 0.f, 0.f, 0.f};
    float d3b[4] = {0.f, 0.f, 0.f, 0.f};
#pragma unroll
    for (int g = 0; g < 16; g++) {
        uint32_t bh[4], bl[4];
        uint32_t brow = ((lid >> 4) << 3) + (lid & 7);
        uint32_t baddr = smb + SM_W3H + brow * 528 + (g * 16 + (lid & 8)) * 2;
        LDSM4(bh, baddr);
        LDSM4(bl, baddr + (SM_W3L - SM_W3H));
        MMA(d3a, a3h[g], bh[0], bh[1]);
        MMA(d3a, a3h[g], bl[0], bl[1]);
        MMA(d3a, a3l[g], bh[0], bh[1]);
        MMA(d3b, a3h[g], bh[2], bh[3]);
        MMA(d3b, a3h[g], bl[2], bl[3]);
        MMA(d3b, a3l[g], bh[2], bh[3]);
    }

    // ---- epilogue: add b3B, store pB, folded iteration count ----
    float pbA[4], pbB[4];   // rows r, r+8; cols {cq, cq+1, 8+cq, 8+cq+1}
    {
        const float* b3s = (const float*)(sm + SM_B3B);
        float2 bva = *(const float2*)&b3s[cq];
        float2 bvb = *(const float2*)&b3s[8 + cq];
        pbA[0] = d3a[0] + bva.x; pbA[1] = d3a[1] + bva.y;
        pbA[2] = d3b[0] + bvb.x; pbA[3] = d3b[1] + bvb.y;
        pbB[0] = d3a[2] + bva.x; pbB[1] = d3a[3] + bva.y;
        pbB[2] = d3b[2] + bvb.x; pbB[3] = d3b[3] + bvb.y;
        int r = row0 + slab + r0;
        *(float2*)&g_pB[r * CD + cq]           = make_float2(pbA[0], pbA[1]);
        *(float2*)&g_pB[r * CD + 8 + cq]       = make_float2(pbA[2], pbA[3]);
        *(float2*)&g_pB[(r + 8) * CD + cq]     = make_float2(pbB[0], pbB[1]);
        *(float2*)&g_pB[(r + 8) * CD + 8 + cq] = make_float2(pbB[2], pbB[3]);
    }
    {
        float u0[4] = {0.f, 0.f, 0.f, 0.f}, u8[4] = {0.f, 0.f, 0.f, 0.f};
        int k0 = 200, k8 = 200, i = 0;
        bool act0 = true, act8 = true;
        while (__any_sync(0xffffffffu, act0 || act8) && i < 200) {
            float s20 = 0.f, s28 = 0.f;
#pragma unroll
            for (int j = 0; j < 4; j++) {
                float s  = u0[j] + pbA[j];
                float un = __fsub_rn(u0[j], __fmul_rn(0.1f, s));
                un = fminf(fmaxf(un, -1.0f), 1.0f);
                float dd = un - u0[j]; s20 += dd * dd; u0[j] = un;
                s  = u8[j] + pbB[j];
                un = __fsub_rn(u8[j], __fmul_rn(0.1f, s));
                un = fminf(fmaxf(un, -1.0f), 1.0f);
                dd = un - u8[j]; s28 += dd * dd; u8[j] = un;
            }
            s20 += __shfl_xor_sync(0xffffffffu, s20, 1);
            s20 += __shfl_xor_sync(0xffffffffu, s20, 2);
            s28 += __shfl_xor_sync(0xffffffffu, s28, 1);
            s28 += __shfl_xor_sync(0xffffffffu, s28, 2);
            float res0 = __fdiv_rn(sqrtf(s20), 0.1f);
            float res8 = __fdiv_rn(sqrtf(s28), 0.1f);
            i++;
            if (act0 && res0 < 0.01f) { k0 = i; act0 = false; }
            if (act8 && res8 < 0.01f) { k8 = i; act8 = false; }
        }
        int kk = max(k0, k8);
#pragma unroll
        for (int o = 16; o > 0; o >>= 1)
            kk = max(kk, __shfl_xor_sync(0xffffffffu, kk, o));
        if (lid == 0) atomicMax(&g_K, kk);
    }
}

// ---------------- k_final: u = clamp(-(1 - 0.9^(K+6)) * pB) ----------------
__global__ void k_final(float* __restrict__ out) {
    int row = blockIdx.x * 256 + threadIdx.x;
    int n = g_K + 6;
    float f = -(1.0f - powf(0.9f, (float)n));
    const float4* ip = (const float4*)&g_pB[row * CD];
    float4* op = (float4*)&out[row * CD];
#pragma unroll
    for (int q = 0; q < 4; q++) {
        float4 v = ip[q];
        float4 u;
        u.x = fminf(fmaxf(f * v.x, -1.0f), 1.0f);
        u.y = fminf(fmaxf(f * v.y, -1.0f), 1.0f);
        u.z = fminf(fmaxf(f * v.z, -1.0f), 1.0f);
        u.w = fminf(fmaxf(f * v.w, -1.0f), 1.0f);
        op[q] = u;
    }
}

// ---------------------------------------------------------------------------
extern "C" void kernel_launch(void* const* d_in, const int* in_sizes, int n_in,
                              void* d_out, int out_size) {
    const float* x  = (const float*)d_in[0];
    const float* t  = (const float*)d_in[1];
    const float* W1 = (const float*)d_in[2];
    const float* b1 = (const float*)d_in[3];
    const float* W2 = (const float*)d_in[4];
    const float* b2 = (const float*)d_in[5];
    const float* W3 = (const float*)d_in[6];
    const float* b3 = (const float*)d_in[7];
    const float* Bm = (const float*)d_in[8];
    float* out = (float*)d_out;

    cudaFuncSetAttribute(k_mlp, cudaFuncAttributeMaxDynamicSharedMemorySize, SM_TOTAL);

    k_prep<<<CD + 1, 256>>>(W3, b3, Bm);
    k_mlp<<<BATCH / 128, 256, SM_TOTAL>>>(x, t, W1, b1, W2, b2);
    k_final<<<BATCH / 256, 256>>>(out);
}

// round 11
// speedup vs baseline: 1.2002x; 1.2002x over previous
#include <cuda_runtime.h>
#include <cuda_bf16.h>
#include <math.h>
#include <cstdint>

#define BATCH 131072
#define SD 64
#define CD 16
#define HID 256

// ---------------- smem layout (bytes) ----------------
#define SM_A2H   0         // 128 rows x 264 halves (528B stride) = 67584
#define SM_A2L   67584
#define SM_WH    135168    // 256 n-rows x 72 halves (144B stride) = 36864
#define SM_WL    172032
#define SM_W3H   135168    // reuse W buffer: 16 x 264 halves (528B) = 8448
#define SM_W3L   143616
#define SM_B1    208896    // 256 f32
#define SM_B2    209920    // 256 f32
#define SM_B3B   210944    // 16 f32
#define SM_TOTAL 211008

// ---------------- scratch globals ----------------
__device__ float g_W3B[HID * CD];
__device__ float g_b3B[CD];
__device__ float g_pB[BATCH * CD];
__device__ int   g_K;

// ---------------- helpers ----------------
__device__ __forceinline__ uint32_t smem_u32(const void* p) {
    uint32_t a;
    asm("{ .reg .u64 t; cvta.to.shared.u64 t, %1; cvt.u32.u64 %0, t; }" : "=r"(a) : "l"(p));
    return a;
}

// split (a,b) f32 pair into packed bf16x2 hi + lo (residual)
__device__ __forceinline__ void split2(float a, float b, uint32_t& hi, uint32_t& lo) {
    __nv_bfloat16 ha = __float2bfloat16(a), hb = __float2bfloat16(b);
    float ra = a - __bfloat162float(ha);
    float rb = b - __bfloat162float(hb);
    __nv_bfloat16 la = __float2bfloat16(ra), lb = __float2bfloat16(rb);
    hi = ((uint32_t)__bfloat16_as_ushort(hb) << 16) | (uint32_t)__bfloat16_as_ushort(ha);
    lo = ((uint32_t)__bfloat16_as_ushort(lb) << 16) | (uint32_t)__bfloat16_as_ushort(la);
}

#define LDSM4(v, addr) \
    asm volatile("ldmatrix.sync.aligned.m8n8.x4.shared.b16 {%0,%1,%2,%3}, [%4];" \
        : "=r"((v)[0]), "=r"((v)[1]), "=r"((v)[2]), "=r"((v)[3]) : "r"(addr))

#define MMA(d, a, b0, b1) \
    asm volatile("mma.sync.aligned.m16n8k16.row.col.f32.bf16.bf16.f32 " \
        "{%0,%1,%2,%3}, {%4,%5,%6,%7}, {%8,%9}, {%0,%1,%2,%3};" \
        : "+f"((d)[0]), "+f"((d)[1]), "+f"((d)[2]), "+f"((d)[3]) \
        : "r"((a)[0]), "r"((a)[1]), "r"((a)[2]), "r"((a)[3]), "r"(b0), "r"(b1))

// ---------------- k_prep: parallel W3B = W3 @ Bmat (smem-staged, coalesced) ----
// blocks 0..15: column j = blockIdx.x; W3 staged to smem coalesced, then each
// thread computes one row's dot from smem. Block 16: b3B + reset g_K.
__global__ void k_prep(const float* __restrict__ W3, const float* __restrict__ b3,
                       const float* __restrict__ Bm) {
    __shared__ float W3s[HID * SD];     // 64 KB
    __shared__ float Bcol[SD];
    int blk = blockIdx.x;
    int tid = threadIdx.x;
    if (blk < CD) {
        int j = blk;
        // coalesced stage of W3 (256x64 f32) via float4
        const float4* src = (const float4*)W3;
#pragma unroll
        for (int i = 0; i < 16; i++)
            ((float4*)W3s)[tid + i * 256] = src[tid + i * 256];
        if (tid < SD) Bcol[tid] = Bm[tid * CD + j];
        __syncthreads();
        float a = 0.0f;
        const float* row = &W3s[tid * SD];
#pragma unroll
        for (int d = 0; d < SD; d++) a = fmaf(row[d], Bcol[d], a);
        g_W3B[tid * CD + j] = a;
    } else {
        if (tid < CD) {
            float a = 0.0f;
            for (int d = 0; d < SD; d++) a = fmaf(b3[d], Bm[d * CD + tid], a);
            g_b3B[tid] = a;
        }
        if (tid == 0) g_K = 0;
    }
}

// stage W chunk [64 k x 256 n] f32 -> Wt[n][k] bf16 hi/lo
__device__ __forceinline__ void load_wchunk(char* sm, const float* __restrict__ W,
                                            int krow0, int tid) {
    int n = tid;
#pragma unroll
    for (int it = 0; it < 8; it++) {
        int kb = krow0 + it * 8;
        uint32_t h[4], l[4];
#pragma unroll
        for (int q = 0; q < 4; q++) {
            float w0 = W[(kb + 2 * q) * HID + n];
            float w1 = W[(kb + 2 * q + 1) * HID + n];
            split2(w0, w1, h[q], l[q]);
        }
        *(uint4*)(sm + SM_WH + n * 144 + it * 16) = make_uint4(h[0], h[1], h[2], h[3]);
        *(uint4*)(sm + SM_WL + n * 144 + it * 16) = make_uint4(l[0], l[1], l[2], l[3]);
    }
}

// ---------------- fused MLP via mma.sync (R6 core, unchanged) ----------------
__global__ void __launch_bounds__(256, 1) k_mlp(
    const float* __restrict__ x, const float* __restrict__ t,
    const float* __restrict__ W1, const float* __restrict__ b1,
    const float* __restrict__ W2, const float* __restrict__ b2)
{
    extern __shared__ char sm[];
    uint32_t smb = smem_u32(sm);
    int tid = threadIdx.x, wid = tid >> 5, lid = tid & 31;
    int slab = wid * 16;
    int row0 = blockIdx.x * 128;
    int r0 = lid >> 2, cq = 2 * (lid & 3);

    // coop: biases + W1 chunk
    float t0 = t[0];
    ((float*)(sm + SM_B1))[tid] = fmaf(t0, W1[64 * HID + tid], b1[tid]);
    ((float*)(sm + SM_B2))[tid] = b2[tid];
    if (tid < CD) ((float*)(sm + SM_B3B))[tid] = g_b3B[tid];
    load_wchunk(sm, W1, 0, tid);

    // per-warp: stage own 16 rows of X into own region of A2H, stride 68 f32
    float* Xs = (float*)(sm + SM_A2H + wid * 8448);
#pragma unroll
    for (int i = 0; i < 8; i++) {
        int fid = i * 32 + lid;
        int r = fid >> 4, c4 = fid & 15;
        float4 v = *(const float4*)&x[(row0 + slab + r) * SD + c4 * 4];
        *(float4*)&Xs[r * 68 + c4 * 4] = v;
    }
    __syncwarp();

    // X fragments (bf16 hi/lo) in regs: 4 k-tiles
    uint32_t xh[4][4], xl[4][4];
#pragma unroll
    for (int kt = 0; kt < 4; kt++) {
        int cb = kt * 16 + cq;
        float2 v00 = *(float2*)&Xs[r0 * 68 + cb];
        float2 v10 = *(float2*)&Xs[(r0 + 8) * 68 + cb];
        float2 v01 = *(float2*)&Xs[r0 * 68 + cb + 8];
        float2 v11 = *(float2*)&Xs[(r0 + 8) * 68 + cb + 8];
        split2(v00.x, v00.y, xh[kt][0], xl[kt][0]);
        split2(v10.x, v10.y, xh[kt][1], xl[kt][1]);
        split2(v01.x, v01.y, xh[kt][2], xl[kt][2]);
        split2(v11.x, v11.y, xh[kt][3], xl[kt][3]);
    }
    __syncwarp();
    __syncthreads();

    // ---- Layer 1: D[16x256] = X @ W1 (bf16 3-product) ----
    float d[32][4];
#pragma unroll
    for (int m = 0; m < 32; m++)
#pragma unroll
        for (int q = 0; q < 4; q++) d[m][q] = 0.0f;

#pragma unroll
    for (int kt = 0; kt < 4; kt++) {
#pragma unroll
        for (int n2 = 0; n2 < 16; n2++) {
            uint32_t bh[4], bl[4];
            uint32_t brow = n2 * 16 + ((lid >> 4) << 3) + (lid & 7);
            uint32_t baddr = smb + SM_WH + brow * 144 + (kt * 16 + (lid & 8)) * 2;
            LDSM4(bh, baddr);
            LDSM4(bl, baddr + (SM_WL - SM_WH));
            MMA(d[2 * n2],     xh[kt], bh[0], bh[1]);
            MMA(d[2 * n2],     xh[kt], bl[0], bl[1]);
            MMA(d[2 * n2],     xl[kt], bh[0], bh[1]);
            MMA(d[2 * n2 + 1], xh[kt], bh[2], bh[3]);
            MMA(d[2 * n2 + 1], xh[kt], bl[2], bl[3]);
            MMA(d[2 * n2 + 1], xl[kt], bh[2], bh[3]);
        }
    }

    // ---- relu + bias1 -> A2 (warp-private smem, bf16 hi/lo) ----
    {
        const float* bs1 = (const float*)(sm + SM_B1);
#pragma unroll
        for (int m = 0; m < 32; m++) {
            int c = m * 8 + cq;
            float2 bv = *(const float2*)&bs1[c];
            float h0 = fmaxf(d[m][0] + bv.x, 0.0f);
            float h1 = fmaxf(d[m][1] + bv.y, 0.0f);
            float h2 = fmaxf(d[m][2] + bv.x, 0.0f);
            float h3 = fmaxf(d[m][3] + bv.y, 0.0f);
            uint32_t hi01, lo01, hi23, lo23;
            split2(h0, h1, hi01, lo01);
            split2(h2, h3, hi23, lo23);
            int ra = slab + r0;
            *(uint32_t*)(sm + SM_A2H + ra * 528 + c * 2) = hi01;
            *(uint32_t*)(sm + SM_A2L + ra * 528 + c * 2) = lo01;
            *(uint32_t*)(sm + SM_A2H + (ra + 8) * 528 + c * 2) = hi23;
            *(uint32_t*)(sm + SM_A2L + (ra + 8) * 528 + c * 2) = lo23;
        }
    }
    __syncthreads();

    // zero accum for layer 2
#pragma unroll
    for (int m = 0; m < 32; m++)
#pragma unroll
        for (int q = 0; q < 4; q++) d[m][q] = 0.0f;

    // ---- Layer 2: 4 K-chunks of 64 (bf16 3-product) ----
#pragma unroll 1
    for (int kc = 0; kc < 4; kc++) {
        load_wchunk(sm, W2, kc * 64, tid);
        __syncthreads();
#pragma unroll
        for (int kt = 0; kt < 4; kt++) {
            uint32_t ah[4], al[4];
            uint32_t arow = slab + (lid & 15);
            uint32_t acol = kc * 64 + kt * 16 + ((lid >> 4) << 3);
            uint32_t aaddr = smb + SM_A2H + arow * 528 + acol * 2;
            LDSM4(ah, aaddr);
            LDSM4(al, aaddr + (SM_A2L - SM_A2H));
#pragma unroll
            for (int n2 = 0; n2 < 16; n2++) {
                uint32_t bh[4], bl[4];
                uint32_t brow = n2 * 16 + ((lid >> 4) << 3) + (lid & 7);
                uint32_t baddr = smb + SM_WH + brow * 144 + (kt * 16 + (lid & 8)) * 2;
                LDSM4(bh, baddr);
                LDSM4(bl, baddr + (SM_WL - SM_WH));
                MMA(d[2 * n2],     ah, bh[0], bh[1]);
                MMA(d[2 * n2],     ah, bl[0], bl[1]);
                MMA(d[2 * n2],     al, bh[0], bh[1]);
                MMA(d[2 * n2 + 1], ah, bh[2], bh[3]);
                MMA(d[2 * n2 + 1], ah, bl[2], bl[3]);
                MMA(d[2 * n2 + 1], al, bh[2], bh[3]);
            }
        }
        __syncthreads();
    }

    // ---- stage W3B^T [16n x 256k] bf16 hi/lo into W buffer ----
#pragma unroll
    for (int it = 0; it < 8; it++) {
        int pid = tid + it * 256;
        int n = pid & 15, k2 = pid >> 4;
        float v0 = g_W3B[(2 * k2) * CD + n];
        float v1 = g_W3B[(2 * k2 + 1) * CD + n];
        uint32_t hi, lo;
        split2(v0, v1, hi, lo);
        *(uint32_t*)(sm + SM_W3H + n * 528 + k2 * 4) = hi;
        *(uint32_t*)(sm + SM_W3L + n * 528 + k2 * 4) = lo;
    }
    __syncthreads();

    // ---- relu + bias2 -> A3 fragments (bf16 hi/lo) ----
    uint32_t a3h[16][4], a3l[16][4];
    {
        const float* bs2 = (const float*)(sm + SM_B2);
#pragma unroll
        for (int g = 0; g < 16; g++) {
#pragma unroll
            for (int hh = 0; hh < 2; hh++) {
                int m = 2 * g + hh;
                int c = m * 8 + cq;
                float2 bv = *(const float2*)&bs2[c];
                float h0 = fmaxf(d[m][0] + bv.x, 0.0f);
                float h1 = fmaxf(d[m][1] + bv.y, 0.0f);
                float h2 = fmaxf(d[m][2] + bv.x, 0.0f);
                float h3 = fmaxf(d[m][3] + bv.y, 0.0f);
                split2(h0, h1, a3h[g][2 * hh],     a3l[g][2 * hh]);
                split2(h2, h3, a3h[g][2 * hh + 1], a3l[g][2 * hh + 1]);
            }
        }
    }

    // ---- Layer 3: pB[16x16] = H2 @ W3B (bf16 3-product) ----
    float d3a[4] = {0.f, 0.f, 0.f, 0.f};
    float d3b[4] = {0.f, 0.f, 0.f, 0.f};
#pragma unroll
    for (int g = 0; g < 16; g++) {
        uint32_t bh[4], bl[4];
        uint32_t brow = ((lid >> 4) << 3) + (lid & 7);
        uint32_t baddr = smb + SM_W3H + brow * 528 + (g * 16 + (lid & 8)) * 2;
        LDSM4(bh, baddr);
        LDSM4(bl, baddr + (SM_W3L - SM_W3H));
        MMA(d3a, a3h[g], bh[0], bh[1]);
        MMA(d3a, a3h[g], bl[0], bl[1]);
        MMA(d3a, a3l[g], bh[0], bh[1]);
        MMA(d3b, a3h[g], bh[2], bh[3]);
        MMA(d3b, a3h[g], bl[2], bl[3]);
        MMA(d3b, a3l[g], bh[2], bh[3]);
    }

    // ---- epilogue: add b3B, store pB ----
    {
        const float* b3s = (const float*)(sm + SM_B3B);
        float2 bva = *(const float2*)&b3s[cq];
        float2 bvb = *(const float2*)&b3s[8 + cq];
        int r = row0 + slab + r0;
        float2 v;
        v = make_float2(d3a[0] + bva.x, d3a[1] + bva.y);
        *(float2*)&g_pB[r * CD + cq] = v;
        v = make_float2(d3b[0] + bvb.x, d3b[1] + bvb.y);
        *(float2*)&g_pB[r * CD + 8 + cq] = v;
        v = make_float2(d3a[2] + bva.x, d3a[3] + bva.y);
        *(float2*)&g_pB[(r + 8) * CD + cq] = v;
        v = make_float2(d3b[2] + bvb.x, d3b[3] + bvb.y);
        *(float2*)&g_pB[(r + 8) * CD + 8 + cq] = v;
    }
}

// ---------------- k_count: while-loop replication, sqrt/div removed ----------------
// res >= TOL  <=>  s2 >= (TOL*ALPHA)^2 = 1e-6 (monotone-equivalent compare)
__global__ void k_count() {
    int row = blockIdx.x * 256 + threadIdx.x;
    const float4* pbp = (const float4*)&g_pB[row * CD];
    float pb[16], u[16];
#pragma unroll
    for (int q = 0; q < 4; q++) {
        float4 v = pbp[q];
        pb[4 * q] = v.x; pb[4 * q + 1] = v.y; pb[4 * q + 2] = v.z; pb[4 * q + 3] = v.w;
    }
#pragma unroll
    for (int j = 0; j < 16; j++) u[j] = 0.0f;

    int i = 0;
    float s2 = __int_as_float(0x7f800000);   // +inf
    while (s2 >= 1e-6f && i < 200) {
        s2 = 0.0f;
#pragma unroll
        for (int j = 0; j < 16; j++) {
            float s  = u[j] + pb[j];
            float un = __fsub_rn(u[j], __fmul_rn(0.1f, s));
            un = fminf(fmaxf(un, -1.0f), 1.0f);
            float dd = un - u[j];
            s2 += dd * dd;
            u[j] = un;
        }
        i++;
    }
    int v = i;
#pragma unroll
    for (int o = 16; o > 0; o >>= 1)
        v = max(v, __shfl_xor_sync(0xffffffffu, v, o));
    if ((threadIdx.x & 31) == 0) atomicMax(&g_K, v);
}

// ---------------- k_final: u = clamp(-(1 - 0.9^(K+6)) * pB) ----------------
__global__ void k_final(float* __restrict__ out) {
    int row = blockIdx.x * 256 + threadIdx.x;
    int n = g_K + 6;
    float f = -(1.0f - powf(0.9f, (float)n));
    const float4* ip = (const float4*)&g_pB[row * CD];
    float4* op = (float4*)&out[row * CD];
#pragma unroll
    for (int q = 0; q < 4; q++) {
        float4 v = ip[q];
        float4 u;
        u.x = fminf(fmaxf(f * v.x, -1.0f), 1.0f);
        u.y = fminf(fmaxf(f * v.y, -1.0f), 1.0f);
        u.z = fminf(fmaxf(f * v.z, -1.0f), 1.0f);
        u.w = fminf(fmaxf(f * v.w, -1.0f), 1.0f);
        op[q] = u;
    }
}

// ---------------------------------------------------------------------------
extern "C" void kernel_launch(void* const* d_in, const int* in_sizes, int n_in,
                              void* d_out, int out_size) {
    const float* x  = (const float*)d_in[0];
    const float* t  = (const float*)d_in[1];
    const float* W1 = (const float*)d_in[2];
    const float* b1 = (const float*)d_in[3];
    const float* W2 = (const float*)d_in[4];
    const float* b2 = (const float*)d_in[5];
    const float* W3 = (const float*)d_in[6];
    const float* b3 = (const float*)d_in[7];
    const float* Bm = (const float*)d_in[8];
    float* out = (float*)d_out;

    cudaFuncSetAttribute(k_mlp, cudaFuncAttributeMaxDynamicSharedMemorySize, SM_TOTAL);

    k_prep<<<CD + 1, 256>>>(W3, b3, Bm);
    k_mlp<<<BATCH / 128, 256, SM_TOTAL>>>(x, t, W1, b1, W2, b2);
    k_count<<<BATCH / 256, 256>>>();
    k_final<<<BATCH / 256, 256>>>(out);
}